// round 4
// baseline (speedup 1.0000x reference)
#include <cuda_runtime.h>
#include <math.h>

#define DD    1024
#define KK    32      // elements per thread
#define PAD   33      // padded shared stride (conflict-free transpose)
#define WARPS 8
#define STACK 4

// In-register FWHT over the 5 bits of the register index k.
// Works for both phases: when thread holds elements (k*32+lane) this covers
// element strides 32..512; when it holds (lane*32+k) it covers strides 1..16.
// Butterfly stages over distinct bits commute, so phase order is free.
__device__ __forceinline__ void fwht_reg(float v[KK]) {
#pragma unroll
    for (int b = 1; b < KK; b <<= 1) {
#pragma unroll
        for (int k = 0; k < KK; k++) {
            if ((k & b) == 0) {
                float a0 = v[k], a1 = v[k | b];
                v[k]     = a0 + a1;
                v[k | b] = a0 - a1;
            }
        }
    }
}

__global__ __launch_bounds__(WARPS * 32)
void FastFoodLayerDense_kernel(const float* __restrict__ x,
                               const float* __restrict__ Bm,
                               const float* __restrict__ G,
                               const float* __restrict__ S,
                               const float* __restrict__ bias,
                               const int*   __restrict__ P,
                               float*       __restrict__ out,
                               int nrows)
{
    __shared__ float sh[WARPS][KK * PAD];   // 33.8 KB static

    const int warp = threadIdx.x >> 5;
    const int lane = threadIdx.x & 31;
    const int unit = blockIdx.x * WARPS + warp;   // (row, stack) pair
    const int row  = unit >> 2;
    const int s    = unit & 3;
    if (row >= nrows) return;                     // warp-uniform

    float* shw = sh[warp];
    const float* xr = x  + (size_t)row * DD;
    const float* Bs = Bm + s * DD;

    float v[KK];

    // ---- load x * B, lane-minor layout: v[k] = element (k*32 + lane) ----
    // Fully coalesced: per k, lanes read consecutive floats.
#pragma unroll
    for (int k = 0; k < KK; k++) {
        int e = k * 32 + lane;
        v[k] = xr[e] * Bs[e];
    }

    // ---- WHT #1: high strides (32..512) in registers ----
    fwht_reg(v);

    // ---- transpose lane-minor -> contiguous via padded shared ----
    __syncwarp();
#pragma unroll
    for (int k = 0; k < KK; k++) shw[k * PAD + lane] = v[k];   // elem k*32+lane
    __syncwarp();
#pragma unroll
    for (int k = 0; k < KK; k++) v[k] = shw[lane * PAD + k];   // elem lane*32+k

    // ---- WHT #1: low strides (1..16) in registers ----
    fwht_reg(v);

    // ---- stage WHT1 result to shared (element order), permute-gather * G ----
    __syncwarp();
#pragma unroll
    for (int k = 0; k < KK; k++) shw[lane * PAD + k] = v[k];   // elem lane*32+k
    __syncwarp();

    const int*   Ps = P + s * DD;
    const float* Gs = G + s * DD;
#pragma unroll
    for (int k = 0; k < KK; k++) {
        int e = lane * 32 + k;
        int p = Ps[e] - s * DD;            // P segment s maps within stack s
        v[k] = shw[p + (p >> 5)] * Gs[e];  // sh[(p>>5)*33 + (p&31)]
    }

    // ---- WHT #2: low strides (contiguous layout) ----
    fwht_reg(v);

    // ---- transpose contiguous -> lane-minor ----
    __syncwarp();
#pragma unroll
    for (int k = 0; k < KK; k++) shw[lane * PAD + k] = v[k];   // elem lane*32+k
    __syncwarp();
#pragma unroll
    for (int k = 0; k < KK; k++) v[k] = shw[k * PAD + lane];   // elem k*32+lane

    // ---- WHT #2: high strides ----
    fwht_reg(v);

    // ---- scale, cos/sin, coalesced stores ----
    const float* Ss  = S + s * DD;
    float* orow      = out + (size_t)row * (2 * STACK * DD);
    const float scale = 0.03125f;   // 1/(sigma*sqrt(D)) = 1/32
    const float amp   = 0.03125f;   // sqrt(1/D) = 1/32
#pragma unroll
    for (int k = 0; k < KK; k++) {
        int e = k * 32 + lane;
        float h = v[k] * scale * Ss[e];
        float sn, cs;
        sincosf(h, &sn, &cs);
        int oc = s * DD + e;
        orow[oc]              = amp * cs + bias[oc];
        orow[STACK * DD + oc] = amp * sn + bias[STACK * DD + oc];
    }
}

extern "C" void kernel_launch(void* const* d_in, const int* in_sizes, int n_in,
                              void* d_out, int out_size)
{
    // metadata order: x, B, G, S, bias, H (unused), P
    const float* x    = (const float*)d_in[0];
    const float* Bm   = (const float*)d_in[1];
    const float* G    = (const float*)d_in[2];
    const float* S    = (const float*)d_in[3];
    const float* bias = (const float*)d_in[4];
    const int*   P    = (const int*)  d_in[6];

    int nrows  = in_sizes[0] / DD;          // 8192
    int units  = nrows * STACK;             // 32768 warps
    int blocks = (units + WARPS - 1) / WARPS;

    FastFoodLayerDense_kernel<<<blocks, WARPS * 32>>>(
        x, Bm, G, S, bias, P, (float*)d_out, nrows);
}